// round 13
// baseline (speedup 1.0000x reference)
#include <cuda_runtime.h>
#include <math.h>

#define B_    32
#define H_    6
#define W_    2400
#define C_    64
#define OV_   4
#define G_    3
#define NVQ_  6
#define K_    1024
#define D_    8
#define FIX_  384
#define GD_   512
#define T_    600
#define NPG   (B_*T_)              // 19200
#define NPTS  (G_*NPG)             // 57600
#define ZQ_SIZE  (B_*H_*W_*C_)     // 29491200
#define IDX_SIZE (B_*NVQ_*G_*T_)   // 345600
#define RVQ_BLOCKS 1800

__device__ float g_en8s[G_*NVQ_*K_*D_];  // 8-split rvq codebooks
__device__ float g_pd2 [G_*D_*GD_];      // pd repacked: [g][j4][dp][dim0..3 x {2dp,2dp+1}]
__device__ float g_zd [G_*NPG*D_];
__device__ float g_zqd[G_*NPG*D_];
__device__ float g_partial[RVQ_BLOCKS];

// ---------------------------------------------------------------------------
// K0: dummy to steer ncu capture window (4th launch = k_down).
// ---------------------------------------------------------------------------
__global__ void k_dummy() {
    if (threadIdx.x == 0) g_partial[0] = 0.f;
}

// ---------------------------------------------------------------------------
// K1: normalize codebook rows, 8-split layout (unchanged from R10).
// ---------------------------------------------------------------------------
__global__ void k_norm(const float* __restrict__ cb) {
    int r = blockIdx.x * blockDim.x + threadIdx.x;
    if (r >= G_*NVQ_*K_) return;
    const float* src = cb + (size_t)r * D_;
    float v[8]; float ss = 0.f;
#pragma unroll
    for (int d = 0; d < 8; d++) { v[d] = src[d]; ss = fmaf(v[d], v[d], ss); }
    float inv = 1.0f / fmaxf(sqrtf(ss), 1e-12f);
    int gi = r >> 10, k = r & 1023;
    int s = k >> 7, jl = (k & 127) >> 1, half = k & 1;
    float* d2 = g_en8s + (size_t)gi*(K_*D_) + jl*128 + s*4 + half;
#pragma unroll
    for (int d = 0; d < 8; d++)
        d2[(d >> 1)*32 + (d & 1)*2] = v[d] * inv;
}

// ---------------------------------------------------------------------------
// K1b: repack proj_down into d-pair-interleaved layout for FFMA2:
// g_pd2[g*4096 + j4*32 + dp*8 + dim*2 + half] = pd[g*8 + 2dp+half][4*j4+dim]
// ---------------------------------------------------------------------------
__global__ void k_prep(const float* __restrict__ pd) {
    int r = blockIdx.x * blockDim.x + threadIdx.x;
    if (r >= G_*512) return;
    int g = r >> 9, rem = r & 511;
    int dp = rem >> 7, j4 = rem & 127;
    const float* s0 = pd + (size_t)(g*8 + 2*dp)*GD_ + 4*j4;
    const float* s1 = s0 + GD_;
    float* d = g_pd2 + g*4096 + j4*32 + dp*8;
#pragma unroll
    for (int m = 0; m < 4; m++) { d[m*2] = s0[m]; d[m*2+1] = s1[m]; }
}

// ---------------------------------------------------------------------------
// K2 v4: pre_process + proj_down. Block = 288 thr = 3 g-warps x (8t x 4dp),
// tile = 24 t (full dims staged once, 197KB smem). Compute: thread = (g,t,dp),
// one f32x2 accumulator; all smem reads are 1-wavefront broadcasts.
// ---------------------------------------------------------------------------
#define ZROW 1540
#define KD_SMEM ((24*ZROW + G_*4096) * 4)   // 196992 bytes

__global__ void __launch_bounds__(288) k_down(const float* __restrict__ ze,
                                              const float* __restrict__ unused) {
    extern __shared__ float sm[];
    float* sZ = sm;                 // [24][ZROW]
    float* sP = sm + 24*ZROW;       // [G][4096]
    int bid  = blockIdx.x;
    int b    = bid / 25;
    int tile = bid % 25;
    int t0   = tile * 24;
    int w0   = t0 * 4;
    int tid  = threadIdx.x;

    // pd2 -> smem (12288 floats)
    for (int idx = tid; idx < G_*4096; idx += 288) sP[idx] = g_pd2[idx];

    // stage z tile: paired-h float2 scatter (96 w x 64 c per h-pair)
#pragma unroll
    for (int hp = 0; hp < 3; hp++) {
        const float* s0 = ze + ((size_t)(b*H_ + 2*hp    )*W_ + w0) * C_;
        const float* s1 = ze + ((size_t)(b*H_ + 2*hp + 1)*W_ + w0) * C_;
        for (int e = tid; e < 96*64; e += 288) {
            float v0 = s0[e], v1 = s1[e];
            int wl = e >> 6, c = e & 63;
            int tl = wl >> 2, o = wl & 3;
            *(float2*)(sZ + tl*ZROW + o*FIX_ + c*6 + 2*hp) = make_float2(v0, v1);
        }
    }
    __syncthreads();

    int w  = tid >> 5, l = tid & 31;
    int g  = w / 3;                       // 9 warps: 3 per group
    int tl = (w % 3)*8 + (l >> 2);        // 0..23
    int dp = l & 3;

    const float* zr = sZ + tl*ZROW + g*GD_;
    const ulonglong2* pg = (const ulonglong2*)(sP + g*4096);

    unsigned long long acc;
    asm("mov.b64 %0, {%1, %1};" : "=l"(acc) : "f"(0.0f));

#pragma unroll 4
    for (int j4 = 0; j4 < 128; j4++) {
        float4 z4 = *(const float4*)(zr + j4*4);
        unsigned long long zx, zy, zz, zw;
        asm("mov.b64 %0, {%1, %1};" : "=l"(zx) : "f"(z4.x));
        asm("mov.b64 %0, {%1, %1};" : "=l"(zy) : "f"(z4.y));
        asm("mov.b64 %0, {%1, %1};" : "=l"(zz) : "f"(z4.z));
        asm("mov.b64 %0, {%1, %1};" : "=l"(zw) : "f"(z4.w));
        ulonglong2 uA = pg[j4*8 + dp*2];
        ulonglong2 uB = pg[j4*8 + dp*2 + 1];
        asm("fma.rn.f32x2 %0, %1, %2, %0;" : "+l"(acc) : "l"(zx), "l"(uA.x));
        asm("fma.rn.f32x2 %0, %1, %2, %0;" : "+l"(acc) : "l"(zy), "l"(uA.y));
        asm("fma.rn.f32x2 %0, %1, %2, %0;" : "+l"(acc) : "l"(zz), "l"(uB.x));
        asm("fma.rn.f32x2 %0, %1, %2, %0;" : "+l"(acc) : "l"(zw), "l"(uB.y));
    }
    float a0, a1;
    asm("mov.b64 {%0, %1}, %2;" : "=f"(a0), "=f"(a1) : "l"(acc));
    *(float2*)(g_zd + ((size_t)g*NPG + b*T_ + t0 + tl)*D_ + 2*dp) = make_float2(a0, a1);
}

// ---------------------------------------------------------------------------
// K3: residual VQ (R10 version: 64 thr = 8 slots x 8 splits, 4 pts/thread).
// ---------------------------------------------------------------------------
__device__ __forceinline__ int combine8(float best, int bk) {
    unsigned bits = __float_as_uint(best);
    unsigned su = bits ^ (unsigned)(((int)bits >> 31) | 0x80000000);
    unsigned long long key = ((unsigned long long)su << 10) | (unsigned)(1023 - bk);
    unsigned long long o = __shfl_xor_sync(0xffffffffu, key, 1);
    key = (o > key) ? o : key;
    o = __shfl_xor_sync(0xffffffffu, key, 2);
    key = (o > key) ? o : key;
    o = __shfl_xor_sync(0xffffffffu, key, 4);
    key = (o > key) ? o : key;
    return 1023 - (int)(key & 1023u);
}

__global__ void __launch_bounds__(64, 7) k_rvq(float* __restrict__ out_codes) {
    __shared__ float sE[K_*D_];
    __shared__ float sWarp[2];
    int bid  = blockIdx.x;
    int g    = bid / (RVQ_BLOCKS/G_);
    int lb   = bid % (RVQ_BLOCKS/G_);
    int tid  = threadIdx.x;
    int slot = tid >> 3;
    int s    = tid & 7;
    int pl0  = lb*32 + slot*4;
    int p0   = g*NPG + pl0;

    unsigned long long r2[4][8];
    {
        const float4* zd4 = (const float4*)g_zd;
#pragma unroll
        for (int m = 0; m < 4; m++) {
            float4 lo = zd4[(size_t)(p0+m)*2], hi = zd4[(size_t)(p0+m)*2+1];
            float rv[8] = { lo.x, lo.y, lo.z, lo.w, hi.x, hi.y, hi.z, hi.w };
#pragma unroll
            for (int d = 0; d < 8; d++)
                asm("mov.b64 %0, {%1, %1};" : "=l"(r2[m][d]) : "f"(rv[d]));
        }
    }
    int ofs[4];
#pragma unroll
    for (int m = 0; m < 4; m++) {
        int pl = pl0 + m;
        int b = pl / T_, t = pl - b*T_;
        ofs[m] = (b*NVQ_*G_ + g)*T_ + t;
    }

    float sse = 0.f;

    for (int i = 0; i < NVQ_; i++) {
        __syncthreads();
        {
            const float4* src = (const float4*)(g_en8s + (size_t)(g*NVQ_ + i)*(K_*D_));
            float4* dst = (float4*)sE;
#pragma unroll
            for (int j = 0; j < 32; j++) dst[tid + j*64] = src[tid + j*64];
        }
        __syncthreads();

        const ulonglong2* e2 = (const ulonglong2*)sE;
        float best0 = -3.0e38f, best1 = -3.0e38f, best2v = -3.0e38f, best3 = -3.0e38f;
        int bk0 = 0, bk1 = 0, bk2 = 0, bk3 = 0;
#pragma unroll 2
        for (int j = 0; j < 64; j++) {
            int base = j*32 + s;
            ulonglong2 c0 = e2[base];
            ulonglong2 c1 = e2[base + 8];
            ulonglong2 c2 = e2[base + 16];
            ulonglong2 c3 = e2[base + 24];
#define SIM(mm, ACC) \
            asm("mul.rn.f32x2 %0, %1, %2;"     : "=l"(ACC) : "l"(r2[mm][0]), "l"(c0.x)); \
            asm("fma.rn.f32x2 %0, %1, %2, %0;" : "+l"(ACC) : "l"(r2[mm][1]), "l"(c0.y)); \
            asm("fma.rn.f32x2 %0, %1, %2, %0;" : "+l"(ACC) : "l"(r2[mm][2]), "l"(c1.x)); \
            asm("fma.rn.f32x2 %0, %1, %2, %0;" : "+l"(ACC) : "l"(r2[mm][3]), "l"(c1.y)); \
            asm("fma.rn.f32x2 %0, %1, %2, %0;" : "+l"(ACC) : "l"(r2[mm][4]), "l"(c2.x)); \
            asm("fma.rn.f32x2 %0, %1, %2, %0;" : "+l"(ACC) : "l"(r2[mm][5]), "l"(c2.y)); \
            asm("fma.rn.f32x2 %0, %1, %2, %0;" : "+l"(ACC) : "l"(r2[mm][6]), "l"(c3.x)); \
            asm("fma.rn.f32x2 %0, %1, %2, %0;" : "+l"(ACC) : "l"(r2[mm][7]), "l"(c3.y));
            unsigned long long a0, a1, a2, a3;
            SIM(0, a0) SIM(1, a1) SIM(2, a2) SIM(3, a3)
#undef SIM
            float lo, hi, m;
            int cand;
            asm("mov.b64 {%0, %1}, %2;" : "=f"(lo), "=f"(hi) : "l"(a0));
            m = fmaxf(lo, hi); cand = 2*j + ((hi > lo) ? 1 : 0);
            if (m > best0) { best0 = m; bk0 = cand; }
            asm("mov.b64 {%0, %1}, %2;" : "=f"(lo), "=f"(hi) : "l"(a1));
            m = fmaxf(lo, hi); cand = 2*j + ((hi > lo) ? 1 : 0);
            if (m > best1) { best1 = m; bk1 = cand; }
            asm("mov.b64 {%0, %1}, %2;" : "=f"(lo), "=f"(hi) : "l"(a2));
            m = fmaxf(lo, hi); cand = 2*j + ((hi > lo) ? 1 : 0);
            if (m > best2v) { best2v = m; bk2 = cand; }
            asm("mov.b64 {%0, %1}, %2;" : "=f"(lo), "=f"(hi) : "l"(a3));
            m = fmaxf(lo, hi); cand = 2*j + ((hi > lo) ? 1 : 0);
            if (m > best3) { best3 = m; bk3 = cand; }
        }
        int kk0 = combine8(best0, s*128 + bk0);
        int kk1 = combine8(best1, s*128 + bk1);
        int kk2 = combine8(best2v, s*128 + bk2);
        int kk3 = combine8(best3, s*128 + bk3);

#define UPD(mm, KVAL) { \
            int k = (KVAL); \
            int base = ((k & 127) >> 1)*128 + ((k >> 7) << 2) + (k & 1); \
            float ss = 0.f; \
            _Pragma("unroll") \
            for (int d = 0; d < 8; d++) { \
                float ev = sE[base + (d >> 1)*32 + (d & 1)*2]; \
                float rlo; \
                asm("mov.b64 {%0, _}, %1;" : "=f"(rlo) : "l"(r2[mm][d])); \
                float rn = rlo - ev; \
                asm("mov.b64 %0, {%1, %1};" : "=l"(r2[mm][d]) : "f"(rn)); \
                ss = fmaf(rn, rn, ss); \
            } \
            sse += ss; }
        UPD(0, kk0) UPD(1, kk1) UPD(2, kk2) UPD(3, kk3)
#undef UPD

        if (s == 0) {
            float* oc = out_codes + (size_t)i*(G_*T_);
            oc[ofs[0]] = (float)kk0;
            oc[ofs[1]] = (float)kk1;
            oc[ofs[2]] = (float)kk2;
            oc[ofs[3]] = (float)kk3;
        }
    }

    if (s == 0) {
        const float4* zd4 = (const float4*)g_zd;
        float4* zq4 = (float4*)g_zqd;
#pragma unroll
        for (int m = 0; m < 4; m++) {
            float4 lo = zd4[(size_t)(p0+m)*2], hi = zd4[(size_t)(p0+m)*2+1];
            float zv[8] = { lo.x, lo.y, lo.z, lo.w, hi.x, hi.y, hi.z, hi.w };
            float qv[8];
#pragma unroll
            for (int d = 0; d < 8; d++) {
                float rlo;
                asm("mov.b64 {%0, _}, %1;" : "=f"(rlo) : "l"(r2[m][d]));
                qv[d] = zv[d] - rlo;
            }
            zq4[(size_t)(p0+m)*2]   = make_float4(qv[0], qv[1], qv[2], qv[3]);
            zq4[(size_t)(p0+m)*2+1] = make_float4(qv[4], qv[5], qv[6], qv[7]);
        }
    }

    float c = (s == 0) ? sse : 0.f;
#pragma unroll
    for (int off = 16; off > 0; off >>= 1)
        c += __shfl_down_sync(0xffffffffu, c, off);
    int lane = tid & 31, wid = tid >> 5;
    if (lane == 0) sWarp[wid] = c;
    __syncthreads();
    if (tid == 0) g_partial[bid] = sWarp[0] + sWarp[1];
}

// ---------------------------------------------------------------------------
// K4: proj_up fused with post_process (R5 version, 33us).
// ---------------------------------------------------------------------------
#define TT 25
__global__ void __launch_bounds__(256) k_up(const float* __restrict__ pu, float* __restrict__ out) {
    __shared__ float sZ[G_*TT*D_];
    int bid  = blockIdx.x;
    int b    = bid / (T_/TT);
    int tile = bid % (T_/TT);
    int t0   = tile * TT;
    int tid  = threadIdx.x;

    for (int idx = tid; idx < G_*TT*D_; idx += 256) {
        int g  = idx / (TT*D_);
        int rr = idx % (TT*D_);
        sZ[idx] = g_zqd[((size_t)g*NPG + b*T_ + t0)*D_ + rr];
    }
    __syncthreads();

    int wid = tid >> 5, lane = tid & 31;
    for (int task = wid; task < 48; task += 8) {
        int o   = task / 12;
        int rem = task % 12;
        int h   = rem >> 1;
        int ch  = rem & 1;
        int c   = ch*32 + lane;
        int pp  = o*FIX_ + c*6 + h;
        int g   = pp >> 9;
        const float4* pu4 = (const float4*)pu + (size_t)pp*2;
        float4 pl = __ldg(pu4), ph = __ldg(pu4 + 1);
        float* op = out + ((size_t)(b*H_ + h)*W_ + 4*t0 + o)*C_ + c;
        const float4* zb = (const float4*)(sZ + g*(TT*D_));
#pragma unroll 5
        for (int tl = 0; tl < TT; tl++) {
            float4 zl = zb[tl*2], zh = zb[tl*2 + 1];
            float s0 = zl.x*pl.x, s1 = zl.y*pl.y;
            s0 = fmaf(zl.z, pl.z, s0); s1 = fmaf(zl.w, pl.w, s1);
            s0 = fmaf(zh.x, ph.x, s0); s1 = fmaf(zh.y, ph.y, s1);
            s0 = fmaf(zh.z, ph.z, s0); s1 = fmaf(zh.w, ph.w, s1);
            op[(size_t)tl*4*C_] = s0 + s1;
        }
    }
}

// ---------------------------------------------------------------------------
// K5: final deterministic loss reduction.
// ---------------------------------------------------------------------------
__global__ void k_final(float* __restrict__ d_out) {
    __shared__ float s[512];
    int tid = threadIdx.x;
    float v = 0.f;
    for (int idx = tid; idx < RVQ_BLOCKS; idx += 512) v += g_partial[idx];
    s[tid] = v; __syncthreads();
    for (int off = 256; off > 0; off >>= 1) {
        if (tid < off) s[tid] += s[tid + off];
        __syncthreads();
    }
    if (tid == 0) {
        float loss = s[0] / (float)(G_ * B_ * T_ * D_);
        d_out[ZQ_SIZE + IDX_SIZE]     = loss;
        d_out[ZQ_SIZE + IDX_SIZE + 1] = loss;
    }
}

// ---------------------------------------------------------------------------
extern "C" void kernel_launch(void* const* d_in, const int* in_sizes, int n_in,
                              void* d_out, int out_size) {
    const float* z_e = (const float*)d_in[0];
    const float* pd  = (const float*)d_in[1];
    const float* pu  = (const float*)d_in[2];
    const float* cb  = (const float*)d_in[3];
    float* out = (float*)d_out;

    cudaFuncSetAttribute(k_down, cudaFuncAttributeMaxDynamicSharedMemorySize, KD_SMEM);

    k_dummy<<<1, 32>>>();                               // launch steering
    k_norm<<<(G_*NVQ_*K_ + 255)/256, 256>>>(cb);
    k_prep<<<6, 256>>>(pd);
    k_down<<<B_*25, 288, KD_SMEM>>>(z_e, pd);           // 4th launch -> ncu
    k_rvq<<<RVQ_BLOCKS, 64>>>(out + ZQ_SIZE);
    k_up<<<B_*(T_/TT), 256>>>(pu, out);
    k_final<<<1, 512>>>(out);
}

// round 14
// speedup vs baseline: 1.2376x; 1.2376x over previous
#include <cuda_runtime.h>
#include <math.h>

#define B_    32
#define H_    6
#define W_    2400
#define C_    64
#define OV_   4
#define G_    3
#define NVQ_  6
#define K_    1024
#define D_    8
#define FIX_  384
#define GD_   512
#define T_    600
#define NPG   (B_*T_)              // 19200
#define NPTS  (G_*NPG)             // 57600
#define ZQ_SIZE  (B_*H_*W_*C_)     // 29491200
#define IDX_SIZE (B_*NVQ_*G_*T_)   // 345600
#define RVQ_BLOCKS 1800

__device__ float g_en8s[G_*NVQ_*K_*D_];  // 8-split rvq codebooks
__device__ float g_pd2 [G_*D_*GD_];      // pd repacked for FFMA2
__device__ float g_zd [G_*NPG*D_];
__device__ float g_zqd[G_*NPG*D_];
__device__ float g_partial[RVQ_BLOCKS];

__device__ __forceinline__ unsigned smem_u32(const void* p) {
    return (unsigned)__cvta_generic_to_shared(p);
}

// ---------------------------------------------------------------------------
// K0: dummy to steer ncu capture window (4th launch = k_down).
// ---------------------------------------------------------------------------
__global__ void k_dummy() {
    if (threadIdx.x == 0) g_partial[0] = 0.f;
}

// ---------------------------------------------------------------------------
// K1: normalize codebook rows, 8-split layout.
// ---------------------------------------------------------------------------
__global__ void k_norm(const float* __restrict__ cb) {
    int r = blockIdx.x * blockDim.x + threadIdx.x;
    if (r >= G_*NVQ_*K_) return;
    const float* src = cb + (size_t)r * D_;
    float v[8]; float ss = 0.f;
#pragma unroll
    for (int d = 0; d < 8; d++) { v[d] = src[d]; ss = fmaf(v[d], v[d], ss); }
    float inv = 1.0f / fmaxf(sqrtf(ss), 1e-12f);
    int gi = r >> 10, k = r & 1023;
    int s = k >> 7, jl = (k & 127) >> 1, half = k & 1;
    float* d2 = g_en8s + (size_t)gi*(K_*D_) + jl*128 + s*4 + half;
#pragma unroll
    for (int d = 0; d < 8; d++)
        d2[(d >> 1)*32 + (d & 1)*2] = v[d] * inv;
}

// ---------------------------------------------------------------------------
// K1b: repack proj_down for FFMA2:
// g_pd2[g*4096 + j4*32 + dp*8 + dim*2 + half] = pd[g*8 + 2dp+half][4*j4+dim]
// ---------------------------------------------------------------------------
__global__ void k_prep(const float* __restrict__ pd) {
    int r = blockIdx.x * blockDim.x + threadIdx.x;
    if (r >= G_*512) return;
    int g = r >> 9, rem = r & 511;
    int dp = rem >> 7, j4 = rem & 127;
    const float* s0 = pd + (size_t)(g*8 + 2*dp)*GD_ + 4*j4;
    const float* s1 = s0 + GD_;
    float* d = g_pd2 + g*4096 + j4*32 + dp*8;
#pragma unroll
    for (int m = 0; m < 4; m++) { d[m*2] = s0[m]; d[m*2+1] = s1[m]; }
}

// ---------------------------------------------------------------------------
// K2 v5: pre_process + proj_down. Same tiling/compute as v4, but staging
// goes through cp.async (LDGSTS): no LDG->STS register dependency, so the
// 128 4B copies per thread issue back-to-back instead of serializing on
// DRAM latency.
// ---------------------------------------------------------------------------
#define ZROW 1540
#define KD_SMEM ((24*ZROW + G_*4096) * 4)   // 196992 bytes

__global__ void __launch_bounds__(288) k_down(const float* __restrict__ ze,
                                              const float* __restrict__ unused) {
    extern __shared__ float sm[];
    float* sZ = sm;                 // [24][ZROW]
    float* sP = sm + 24*ZROW;       // [G][4096]
    int bid  = blockIdx.x;
    int b    = bid / 25;
    int tile = bid % 25;
    int t0   = tile * 24;
    int w0   = t0 * 4;
    int tid  = threadIdx.x;

    // pd2 -> smem via cp.async (16B each, 12288 floats)
    for (int idx = tid*4; idx < G_*4096; idx += 288*4) {
        unsigned dst = smem_u32(sP + idx);
        asm volatile("cp.async.ca.shared.global [%0], [%1], 16;"
                     :: "r"(dst), "l"(g_pd2 + idx));
    }

    // stage z tile via 4B cp.async with transpose scatter:
    // z_e[b, h*W + w, c] -> sZ[tl][o*384 + c*6 + h]
#pragma unroll
    for (int h = 0; h < 6; h++) {
        const float* src = ze + ((size_t)(b*H_ + h)*W_ + w0) * C_;
#pragma unroll
        for (int it = 0; it < 96*64/288; it++) {      // 21.33 -> handle remainder below
            int e = tid + it*288;
            int wl = e >> 6, c = e & 63;
            int tl = wl >> 2, o = wl & 3;
            unsigned dst = smem_u32(sZ + tl*ZROW + o*FIX_ + c*6 + h);
            asm volatile("cp.async.ca.shared.global [%0], [%1], 4;"
                         :: "r"(dst), "l"(src + e));
        }
        {   // remainder: e in [6048, 6144)
            int e = tid + (96*64/288)*288;
            if (e < 96*64) {
                int wl = e >> 6, c = e & 63;
                int tl = wl >> 2, o = wl & 3;
                unsigned dst = smem_u32(sZ + tl*ZROW + o*FIX_ + c*6 + h);
                asm volatile("cp.async.ca.shared.global [%0], [%1], 4;"
                             :: "r"(dst), "l"(src + e));
            }
        }
    }
    asm volatile("cp.async.commit_group;" ::: "memory");
    asm volatile("cp.async.wait_group 0;" ::: "memory");
    __syncthreads();

    int w  = tid >> 5, l = tid & 31;
    int g  = w / 3;                       // 9 warps: 3 per group
    int tl = (w % 3)*8 + (l >> 2);        // 0..23
    int dp = l & 3;

    const float* zr = sZ + tl*ZROW + g*GD_;
    const ulonglong2* pg = (const ulonglong2*)(sP + g*4096);

    unsigned long long acc0, acc1;
    asm("mov.b64 %0, {%1, %1};" : "=l"(acc0) : "f"(0.0f));
    asm("mov.b64 %0, {%1, %1};" : "=l"(acc1) : "f"(0.0f));

#pragma unroll 4
    for (int j4 = 0; j4 < 128; j4++) {
        float4 z4 = *(const float4*)(zr + j4*4);
        unsigned long long zx, zy, zz, zw;
        asm("mov.b64 %0, {%1, %1};" : "=l"(zx) : "f"(z4.x));
        asm("mov.b64 %0, {%1, %1};" : "=l"(zy) : "f"(z4.y));
        asm("mov.b64 %0, {%1, %1};" : "=l"(zz) : "f"(z4.z));
        asm("mov.b64 %0, {%1, %1};" : "=l"(zw) : "f"(z4.w));
        ulonglong2 uA = pg[j4*8 + dp*2];
        ulonglong2 uB = pg[j4*8 + dp*2 + 1];
        asm("fma.rn.f32x2 %0, %1, %2, %0;" : "+l"(acc0) : "l"(zx), "l"(uA.x));
        asm("fma.rn.f32x2 %0, %1, %2, %0;" : "+l"(acc1) : "l"(zy), "l"(uA.y));
        asm("fma.rn.f32x2 %0, %1, %2, %0;" : "+l"(acc0) : "l"(zz), "l"(uB.x));
        asm("fma.rn.f32x2 %0, %1, %2, %0;" : "+l"(acc1) : "l"(zw), "l"(uB.y));
    }
    asm("add.rn.f32x2 %0, %0, %1;" : "+l"(acc0) : "l"(acc1));
    float a0, a1;
    asm("mov.b64 {%0, %1}, %2;" : "=f"(a0), "=f"(a1) : "l"(acc0));
    *(float2*)(g_zd + ((size_t)g*NPG + b*T_ + t0 + tl)*D_ + 2*dp) = make_float2(a0, a1);
}

// ---------------------------------------------------------------------------
// K3: residual VQ (R10 version: 64 thr = 8 slots x 8 splits, 4 pts/thread).
// ---------------------------------------------------------------------------
__device__ __forceinline__ int combine8(float best, int bk) {
    unsigned bits = __float_as_uint(best);
    unsigned su = bits ^ (unsigned)(((int)bits >> 31) | 0x80000000);
    unsigned long long key = ((unsigned long long)su << 10) | (unsigned)(1023 - bk);
    unsigned long long o = __shfl_xor_sync(0xffffffffu, key, 1);
    key = (o > key) ? o : key;
    o = __shfl_xor_sync(0xffffffffu, key, 2);
    key = (o > key) ? o : key;
    o = __shfl_xor_sync(0xffffffffu, key, 4);
    key = (o > key) ? o : key;
    return 1023 - (int)(key & 1023u);
}

__global__ void __launch_bounds__(64, 7) k_rvq(float* __restrict__ out_codes) {
    __shared__ float sE[K_*D_];
    __shared__ float sWarp[2];
    int bid  = blockIdx.x;
    int g    = bid / (RVQ_BLOCKS/G_);
    int lb   = bid % (RVQ_BLOCKS/G_);
    int tid  = threadIdx.x;
    int slot = tid >> 3;
    int s    = tid & 7;
    int pl0  = lb*32 + slot*4;
    int p0   = g*NPG + pl0;

    unsigned long long r2[4][8];
    {
        const float4* zd4 = (const float4*)g_zd;
#pragma unroll
        for (int m = 0; m < 4; m++) {
            float4 lo = zd4[(size_t)(p0+m)*2], hi = zd4[(size_t)(p0+m)*2+1];
            float rv[8] = { lo.x, lo.y, lo.z, lo.w, hi.x, hi.y, hi.z, hi.w };
#pragma unroll
            for (int d = 0; d < 8; d++)
                asm("mov.b64 %0, {%1, %1};" : "=l"(r2[m][d]) : "f"(rv[d]));
        }
    }
    int ofs[4];
#pragma unroll
    for (int m = 0; m < 4; m++) {
        int pl = pl0 + m;
        int b = pl / T_, t = pl - b*T_;
        ofs[m] = (b*NVQ_*G_ + g)*T_ + t;
    }

    float sse = 0.f;

    for (int i = 0; i < NVQ_; i++) {
        __syncthreads();
        {
            const float4* src = (const float4*)(g_en8s + (size_t)(g*NVQ_ + i)*(K_*D_));
            float4* dst = (float4*)sE;
#pragma unroll
            for (int j = 0; j < 32; j++) dst[tid + j*64] = src[tid + j*64];
        }
        __syncthreads();

        const ulonglong2* e2 = (const ulonglong2*)sE;
        float best0 = -3.0e38f, best1 = -3.0e38f, best2v = -3.0e38f, best3 = -3.0e38f;
        int bk0 = 0, bk1 = 0, bk2 = 0, bk3 = 0;
#pragma unroll 2
        for (int j = 0; j < 64; j++) {
            int base = j*32 + s;
            ulonglong2 c0 = e2[base];
            ulonglong2 c1 = e2[base + 8];
            ulonglong2 c2 = e2[base + 16];
            ulonglong2 c3 = e2[base + 24];
#define SIM(mm, ACC) \
            asm("mul.rn.f32x2 %0, %1, %2;"     : "=l"(ACC) : "l"(r2[mm][0]), "l"(c0.x)); \
            asm("fma.rn.f32x2 %0, %1, %2, %0;" : "+l"(ACC) : "l"(r2[mm][1]), "l"(c0.y)); \
            asm("fma.rn.f32x2 %0, %1, %2, %0;" : "+l"(ACC) : "l"(r2[mm][2]), "l"(c1.x)); \
            asm("fma.rn.f32x2 %0, %1, %2, %0;" : "+l"(ACC) : "l"(r2[mm][3]), "l"(c1.y)); \
            asm("fma.rn.f32x2 %0, %1, %2, %0;" : "+l"(ACC) : "l"(r2[mm][4]), "l"(c2.x)); \
            asm("fma.rn.f32x2 %0, %1, %2, %0;" : "+l"(ACC) : "l"(r2[mm][5]), "l"(c2.y)); \
            asm("fma.rn.f32x2 %0, %1, %2, %0;" : "+l"(ACC) : "l"(r2[mm][6]), "l"(c3.x)); \
            asm("fma.rn.f32x2 %0, %1, %2, %0;" : "+l"(ACC) : "l"(r2[mm][7]), "l"(c3.y));
            unsigned long long a0, a1, a2, a3;
            SIM(0, a0) SIM(1, a1) SIM(2, a2) SIM(3, a3)
#undef SIM
            float lo, hi, m;
            int cand;
            asm("mov.b64 {%0, %1}, %2;" : "=f"(lo), "=f"(hi) : "l"(a0));
            m = fmaxf(lo, hi); cand = 2*j + ((hi > lo) ? 1 : 0);
            if (m > best0) { best0 = m; bk0 = cand; }
            asm("mov.b64 {%0, %1}, %2;" : "=f"(lo), "=f"(hi) : "l"(a1));
            m = fmaxf(lo, hi); cand = 2*j + ((hi > lo) ? 1 : 0);
            if (m > best1) { best1 = m; bk1 = cand; }
            asm("mov.b64 {%0, %1}, %2;" : "=f"(lo), "=f"(hi) : "l"(a2));
            m = fmaxf(lo, hi); cand = 2*j + ((hi > lo) ? 1 : 0);
            if (m > best2v) { best2v = m; bk2 = cand; }
            asm("mov.b64 {%0, %1}, %2;" : "=f"(lo), "=f"(hi) : "l"(a3));
            m = fmaxf(lo, hi); cand = 2*j + ((hi > lo) ? 1 : 0);
            if (m > best3) { best3 = m; bk3 = cand; }
        }
        int kk0 = combine8(best0, s*128 + bk0);
        int kk1 = combine8(best1, s*128 + bk1);
        int kk2 = combine8(best2v, s*128 + bk2);
        int kk3 = combine8(best3, s*128 + bk3);

#define UPD(mm, KVAL) { \
            int k = (KVAL); \
            int base = ((k & 127) >> 1)*128 + ((k >> 7) << 2) + (k & 1); \
            float ss = 0.f; \
            _Pragma("unroll") \
            for (int d = 0; d < 8; d++) { \
                float ev = sE[base + (d >> 1)*32 + (d & 1)*2]; \
                float rlo; \
                asm("mov.b64 {%0, _}, %1;" : "=f"(rlo) : "l"(r2[mm][d])); \
                float rn = rlo - ev; \
                asm("mov.b64 %0, {%1, %1};" : "=l"(r2[mm][d]) : "f"(rn)); \
                ss = fmaf(rn, rn, ss); \
            } \
            sse += ss; }
        UPD(0, kk0) UPD(1, kk1) UPD(2, kk2) UPD(3, kk3)
#undef UPD

        if (s == 0) {
            float* oc = out_codes + (size_t)i*(G_*T_);
            oc[ofs[0]] = (float)kk0;
            oc[ofs[1]] = (float)kk1;
            oc[ofs[2]] = (float)kk2;
            oc[ofs[3]] = (float)kk3;
        }
    }

    if (s == 0) {
        const float4* zd4 = (const float4*)g_zd;
        float4* zq4 = (float4*)g_zqd;
#pragma unroll
        for (int m = 0; m < 4; m++) {
            float4 lo = zd4[(size_t)(p0+m)*2], hi = zd4[(size_t)(p0+m)*2+1];
            float zv[8] = { lo.x, lo.y, lo.z, lo.w, hi.x, hi.y, hi.z, hi.w };
            float qv[8];
#pragma unroll
            for (int d = 0; d < 8; d++) {
                float rlo;
                asm("mov.b64 {%0, _}, %1;" : "=f"(rlo) : "l"(r2[m][d]));
                qv[d] = zv[d] - rlo;
            }
            zq4[(size_t)(p0+m)*2]   = make_float4(qv[0], qv[1], qv[2], qv[3]);
            zq4[(size_t)(p0+m)*2+1] = make_float4(qv[4], qv[5], qv[6], qv[7]);
        }
    }

    float c = (s == 0) ? sse : 0.f;
#pragma unroll
    for (int off = 16; off > 0; off >>= 1)
        c += __shfl_down_sync(0xffffffffu, c, off);
    int lane = tid & 31, wid = tid >> 5;
    if (lane == 0) sWarp[wid] = c;
    __syncthreads();
    if (tid == 0) g_partial[bid] = sWarp[0] + sWarp[1];
}

// ---------------------------------------------------------------------------
// K4: proj_up fused with post_process (R5 version, 33us).
// ---------------------------------------------------------------------------
#define TT 25
__global__ void __launch_bounds__(256) k_up(const float* __restrict__ pu, float* __restrict__ out) {
    __shared__ float sZ[G_*TT*D_];
    int bid  = blockIdx.x;
    int b    = bid / (T_/TT);
    int tile = bid % (T_/TT);
    int t0   = tile * TT;
    int tid  = threadIdx.x;

    for (int idx = tid; idx < G_*TT*D_; idx += 256) {
        int g  = idx / (TT*D_);
        int rr = idx % (TT*D_);
        sZ[idx] = g_zqd[((size_t)g*NPG + b*T_ + t0)*D_ + rr];
    }
    __syncthreads();

    int wid = tid >> 5, lane = tid & 31;
    for (int task = wid; task < 48; task += 8) {
        int o   = task / 12;
        int rem = task % 12;
        int h   = rem >> 1;
        int ch  = rem & 1;
        int c   = ch*32 + lane;
        int pp  = o*FIX_ + c*6 + h;
        int g   = pp >> 9;
        const float4* pu4 = (const float4*)pu + (size_t)pp*2;
        float4 pl = __ldg(pu4), ph = __ldg(pu4 + 1);
        float* op = out + ((size_t)(b*H_ + h)*W_ + 4*t0 + o)*C_ + c;
        const float4* zb = (const float4*)(sZ + g*(TT*D_));
#pragma unroll 5
        for (int tl = 0; tl < TT; tl++) {
            float4 zl = zb[tl*2], zh = zb[tl*2 + 1];
            float s0 = zl.x*pl.x, s1 = zl.y*pl.y;
            s0 = fmaf(zl.z, pl.z, s0); s1 = fmaf(zl.w, pl.w, s1);
            s0 = fmaf(zh.x, ph.x, s0); s1 = fmaf(zh.y, ph.y, s1);
            s0 = fmaf(zh.z, ph.z, s0); s1 = fmaf(zh.w, ph.w, s1);
            op[(size_t)tl*4*C_] = s0 + s1;
        }
    }
}

// ---------------------------------------------------------------------------
// K5: final deterministic loss reduction.
// ---------------------------------------------------------------------------
__global__ void k_final(float* __restrict__ d_out) {
    __shared__ float s[512];
    int tid = threadIdx.x;
    float v = 0.f;
    for (int idx = tid; idx < RVQ_BLOCKS; idx += 512) v += g_partial[idx];
    s[tid] = v; __syncthreads();
    for (int off = 256; off > 0; off >>= 1) {
        if (tid < off) s[tid] += s[tid + off];
        __syncthreads();
    }
    if (tid == 0) {
        float loss = s[0] / (float)(G_ * B_ * T_ * D_);
        d_out[ZQ_SIZE + IDX_SIZE]     = loss;
        d_out[ZQ_SIZE + IDX_SIZE + 1] = loss;
    }
}

// ---------------------------------------------------------------------------
extern "C" void kernel_launch(void* const* d_in, const int* in_sizes, int n_in,
                              void* d_out, int out_size) {
    const float* z_e = (const float*)d_in[0];
    const float* pd  = (const float*)d_in[1];
    const float* pu  = (const float*)d_in[2];
    const float* cb  = (const float*)d_in[3];
    float* out = (float*)d_out;

    cudaFuncSetAttribute(k_down, cudaFuncAttributeMaxDynamicSharedMemorySize, KD_SMEM);

    k_dummy<<<1, 32>>>();                               // launch steering
    k_norm<<<(G_*NVQ_*K_ + 255)/256, 256>>>(cb);
    k_prep<<<6, 256>>>(pd);
    k_down<<<B_*25, 288, KD_SMEM>>>(z_e, pd);           // 4th launch -> ncu
    k_rvq<<<RVQ_BLOCKS, 64>>>(out + ZQ_SIZE);
    k_up<<<B_*(T_/TT), 256>>>(pu, out);
    k_final<<<1, 512>>>(out);
}